// round 5
// baseline (speedup 1.0000x reference)
#include <cuda_runtime.h>
#include <cstdint>
#include <cstddef>

// ---------------- scratch (__device__ globals; no allocation) ----------------
__device__ float g_app[16384 * 512];
__device__ float g_motproj[1024 * 512];
__device__ float g_qproj[128 * 512];
__device__ float g_mean[14 * 1536 * 512];   // batched mean buffers (max 14 steps)
__device__ float g_objs2[1024 * 14 * 512];
__device__ float g_clip[1024 * 12 * 512];
__device__ float g_gatesx[1024 * 2048];
__device__ float g_gates[128 * 2048];
__device__ float g_hstate[128 * 512];
__device__ float g_cstate[128 * 512];
__device__ float g_vm[128 * 512];
__device__ float g_objs4[128 * 6 * 12 * 512];

struct MaskArgs { unsigned m[14]; float inv[14]; };

// ---------------- SGEMM: C = act(A @ W^T + bias) ----------------------------
// A operand: k < 512 -> Aa[step] rows (lda), else (if Ac) Ac[(m/ac_div)*512 + k-512].
// W is [N,K] row-major. Batched over blockIdx.z with per-operand step strides.
// Output row offset: (m/c_inner)*c_so + (m%c_inner)*c_sr, plus step*C_step.
// act: 0 none | 1 elu | 2 C *= sigmoid(v) | 3 v += add[m*add_sr+n]
// Inner loop: packed fma.rn.f32x2 (2x fp32 FMA throughput on sm_103a).
template<int BM, int TM>
__global__ void __launch_bounds__(256)
sgemm_kernel(const float* __restrict__ Aa, long long Aa_step, int lda,
             const float* __restrict__ Ac, int ac_div,
             const float* __restrict__ W, long long W_step,
             const float* __restrict__ bias, long long bias_step,
             const float* __restrict__ add, long long add_sr,
             float* __restrict__ C, long long C_step,
             int c_inner, long long c_so, long long c_sr,
             int K, int act)
{
    constexpr int BN = BM, TN = TM, BK = 16;
    __shared__ __align__(16) float As[BK][BM];
    __shared__ __align__(16) float Bs[BK][BN];
    const int bm = blockIdx.y * BM, bn = blockIdx.x * BN;
    const int tid = threadIdx.x, tx = tid & 15, ty = tid >> 4;
    const int step = blockIdx.z;
    Aa += (size_t)step * Aa_step;
    W += (size_t)step * W_step;
    bias += (size_t)step * bias_step;
    C += (size_t)step * C_step;

    unsigned long long acc[TM][TN / 2];
#pragma unroll
    for (int i = 0; i < TM; i++)
#pragma unroll
        for (int j = 0; j < TN / 2; j++) acc[i][j] = 0ull;

    constexpr int NIT = (BM * BK / 4) / 256;
    for (int k0 = 0; k0 < K; k0 += BK) {
#pragma unroll
        for (int it = 0; it < NIT; it++) {
            int f = tid + 256 * it, r = f >> 2, c4 = (f & 3) << 2;
            int m = bm + r, k = k0 + c4;
            const float* ap;
            if (Ac && k >= 512) ap = Ac + (size_t)(m / ac_div) * 512 + (k - 512);
            else                ap = Aa + (size_t)m * lda + k;
            float4 va = *(const float4*)ap;
            As[c4 + 0][r] = va.x; As[c4 + 1][r] = va.y;
            As[c4 + 2][r] = va.z; As[c4 + 3][r] = va.w;
            float4 vb = *(const float4*)(W + (size_t)(bn + r) * K + k);
            Bs[c4 + 0][r] = vb.x; Bs[c4 + 1][r] = vb.y;
            Bs[c4 + 2][r] = vb.z; Bs[c4 + 3][r] = vb.w;
        }
        __syncthreads();
#pragma unroll
        for (int kk = 0; kk < BK; kk++) {
            float av[TM];
            float4 a0 = *(const float4*)(&As[kk][ty * 4]);
            av[0] = a0.x; av[1] = a0.y; av[2] = a0.z; av[3] = a0.w;
            if constexpr (TM == 8) {
                float4 a1 = *(const float4*)(&As[kk][BM / 2 + ty * 4]);
                av[4] = a1.x; av[5] = a1.y; av[6] = a1.z; av[7] = a1.w;
            }
            unsigned long long bp[TN / 2];
            double2 b0 = *(const double2*)(&Bs[kk][tx * 4]);
            bp[0] = (unsigned long long)__double_as_longlong(b0.x);
            bp[1] = (unsigned long long)__double_as_longlong(b0.y);
            if constexpr (TN == 8) {
                double2 b1 = *(const double2*)(&Bs[kk][BN / 2 + tx * 4]);
                bp[2] = (unsigned long long)__double_as_longlong(b1.x);
                bp[3] = (unsigned long long)__double_as_longlong(b1.y);
            }
#pragma unroll
            for (int i = 0; i < TM; i++) {
                unsigned long long ap2;
                asm("mov.b64 %0, {%1, %1};" : "=l"(ap2) : "r"(__float_as_uint(av[i])));
#pragma unroll
                for (int j = 0; j < TN / 2; j++)
                    asm("fma.rn.f32x2 %0, %1, %2, %0;"
                        : "+l"(acc[i][j]) : "l"(ap2), "l"(bp[j]));
            }
        }
        __syncthreads();
    }
#pragma unroll
    for (int i = 0; i < TM; i++) {
        int mi = (TM == 8) ? ((i < 4) ? ty * 4 + i : BM / 2 + ty * 4 + (i - 4))
                           : ty * 4 + i;
        int m = bm + mi;
        size_t crow = (size_t)(m / c_inner) * (size_t)c_so
                    + (size_t)(m % c_inner) * (size_t)c_sr;
#pragma unroll
        for (int j = 0; j < TN; j++) {
            int nj = (TN == 8) ? ((j < 4) ? tx * 4 + j : BN / 2 + tx * 4 + (j - 4))
                               : tx * 4 + j;
            int n = bn + nj;
            unsigned long long p = acc[i][j >> 1];
            unsigned lane = (j & 1) ? (unsigned)(p >> 32) : (unsigned)p;
            float v = __uint_as_float(lane) + bias[n];
            float* cp = C + crow + n;
            if (act == 0)      *cp = v;
            else if (act == 1) *cp = (v > 0.f) ? v : expm1f(v);
            else if (act == 2) *cp = *cp * (1.f / (1.f + expf(-v)));
            else { v += add[(size_t)m * add_sr + n]; *cp = v; }
        }
    }
}

// Batched subset-mean over blockIdx.y = step.
// out[step][m][d] = mean over bits j of ma.m[step] of
//   objs[(m/inner)*sB + (m%inner)*sR + j*sJ + d], D=512.
__global__ void mean_subset_batched(float* __restrict__ out,
                                    const float* __restrict__ objs,
                                    int inner, long long sB, long long sR, long long sJ,
                                    MaskArgs ma, int M)
{
    int step = blockIdx.y;
    int idx = blockIdx.x * blockDim.x + threadIdx.x;
    int m = idx >> 7, d4 = (idx & 127) << 2;
    if (m >= M) return;
    unsigned mm = ma.m[step];
    float inv = ma.inv[step];
    const float* base = objs + (size_t)(m / inner) * sB + (size_t)(m % inner) * sR + d4;
    float sx = 0.f, sy = 0.f, sz = 0.f, sw = 0.f;
    while (mm) {
        int j = __ffs((int)mm) - 1; mm &= mm - 1;
        float4 v = *(const float4*)(base + (size_t)j * sJ);
        sx += v.x; sy += v.y; sz += v.z; sw += v.w;
    }
    float4 o = {sx * inv, sy * inv, sz * inv, sw * inv};
    *(float4*)(out + (size_t)step * M * 512 + (size_t)m * 512 + d4) = o;
}

__global__ void zero_kernel(float* p, int n)
{
    int i = blockIdx.x * blockDim.x + threadIdx.x;
    if (i < n) p[i] = 0.f;
}

__global__ void lstm_cell_kernel(const float* __restrict__ gates,
                                 float* __restrict__ h, float* __restrict__ c)
{
    int idx = blockIdx.x * blockDim.x + threadIdx.x;
    int m = idx >> 9, d = idx & 511;
    const float* gr = gates + (size_t)m * 2048;
    float ig = 1.f / (1.f + expf(-gr[d]));
    float fg = 1.f / (1.f + expf(-gr[512 + d]));
    float gg = tanhf(gr[1024 + d]);
    float og = 1.f / (1.f + expf(-gr[1536 + d]));
    float cn = fg * c[idx] + ig * gg;
    c[idx] = cn;
    h[idx] = og * tanhf(cn);
}

// ---------------- host-side exact numpy RandomState(0) replication ----------
namespace {
struct MT19937 {
    unsigned mt[624]; int pos;
    void seed(unsigned s) {
        for (int i = 0; i < 624; i++) { mt[i] = s; s = 1812433253u * (s ^ (s >> 30)) + (unsigned)i + 1u; }
        pos = 624;
    }
    unsigned next() {
        if (pos >= 624) {
            for (int i = 0; i < 624; i++) {
                unsigned y = (mt[i] & 0x80000000u) | (mt[(i + 1) % 624] & 0x7fffffffu);
                unsigned v = mt[(i + 397) % 624] ^ (y >> 1);
                if (y & 1u) v ^= 0x9908b0dfu;
                mt[i] = v;
            }
            pos = 0;
        }
        unsigned y = mt[pos++];
        y ^= y >> 11; y ^= (y << 7) & 0x9d2c5680u; y ^= (y << 15) & 0xefc60000u; y ^= y >> 18;
        return y;
    }
    unsigned interval(unsigned mx) {
        if (!mx) return 0;
        unsigned mask = mx;
        mask |= mask >> 1; mask |= mask >> 2; mask |= mask >> 4; mask |= mask >> 8; mask |= mask >> 16;
        unsigned v; do { v = next() & mask; } while (v > mx);
        return v;
    }
};

static int perm_first(MT19937& r, int n) {
    static int arr[13000];
    for (int i = 0; i < n; i++) arr[i] = i;
    for (int i = n - 1; i > 0; i--) {
        int j = (int)r.interval((unsigned)i);
        int t = arr[i]; arr[i] = arr[j]; arr[j] = t;
    }
    return arr[0];
}

static unsigned unrank_mask(int n, int k, long long idx, const unsigned long long Bn[17][17]) {
    unsigned mask = 0; int x = 0;
    for (int i = 0; i < k; i++)
        for (int v = x;; v++) {
            long long c = (long long)Bn[n - 1 - v][k - 1 - i];
            if (idx < c) { mask |= 1u << v; x = v + 1; break; }
            idx -= c;
        }
    return mask;
}

// Generic non-batched GEMM launch (z = 1)
static void launch_gemm(bool big, const float* A, int lda, const float* W,
                        const float* bias, float* C, int c_inner,
                        long long c_so, long long c_sr,
                        int M, int N, int K, int act,
                        const float* add = nullptr, long long add_sr = 0) {
    if (big) {
        dim3 grid(N / 128, M / 128, 1);
        sgemm_kernel<128, 8><<<grid, 256>>>(A, 0, lda, nullptr, 1, W, 0, bias, 0,
                                            add, add_sr, C, 0, c_inner, c_so, c_sr, K, act);
    } else {
        dim3 grid(N / 64, M / 64, 1);
        sgemm_kernel<64, 4><<<grid, 256>>>(A, 0, lda, nullptr, 1, W, 0, bias, 0,
                                           add, add_sr, C, 0, c_inner, c_so, c_sr, K, act);
    }
}

// Batched CRN GEMM launch: A = [mean(step) | cond], K = 1024
static void launch_crn(const float* meanbuf, const float* cond, int ac_div,
                       const float* Wbank, const float* bbank,
                       float* C, long long C_step,
                       int c_inner, long long c_so, long long c_sr,
                       int M, int steps, int act) {
    dim3 grid(512 / 128, M / 128, steps);
    sgemm_kernel<128, 8><<<grid, 256>>>(
        meanbuf, (long long)M * 512, 512, cond, ac_div,
        Wbank + (size_t)512 * 1024, (long long)512 * 1024,
        bbank + 512, 512,
        nullptr, 0, C, C_step, c_inner, c_so, c_sr, 1024, act);
}
}  // namespace

extern "C" void kernel_launch(void* const* d_in, const int* in_sizes, int n_in,
                              void* d_out, int out_size)
{
    (void)in_sizes; (void)n_in; (void)out_size;
    const float* app = (const float*)d_in[0];
    const float* mot = (const float*)d_in[1];
    const float* qe  = (const float*)d_in[2];
    const float* Wq  = (const float*)d_in[3];
    const float* bq  = (const float*)d_in[4];
    const float* Wm  = (const float*)d_in[5];
    const float* bmv = (const float*)d_in[6];
    const float* Wa  = (const float*)d_in[7];
    const float* ba  = (const float*)d_in[8];
    const float* Wvm = (const float*)d_in[9];
    const float* bvm = (const float*)d_in[10];
    const float* Wih = (const float*)d_in[11];
    const float* Whh = (const float*)d_in[12];
    const float* bih = (const float*)d_in[13];
    const float* bhh = (const float*)d_in[14];
    const float* W1  = (const float*)d_in[15];
    const float* b1  = (const float*)d_in[16];
    const float* W2  = (const float*)d_in[17];
    const float* b2  = (const float*)d_in[18];
    const float* gW2 = (const float*)d_in[19];
    const float* gb2 = (const float*)d_in[20];
    const float* W3  = (const float*)d_in[21];
    const float* b3  = (const float*)d_in[22];
    const float* W4  = (const float*)d_in[23];
    const float* b4  = (const float*)d_in[24];
    const float* gW4 = (const float*)d_in[25];
    const float* gb4 = (const float*)d_in[26];
    float* outp = (float*)d_out;

    // ---- RNG: 36 choice() calls in reference trace order (verified exact) ----
    unsigned long long Bn[17][17] = {};
    for (int i = 0; i <= 16; i++) {
        Bn[i][0] = 1;
        for (int j = 1; j <= i; j++)
            Bn[i][j] = Bn[i - 1][j - 1] + ((j <= i - 1) ? Bn[i - 1][j] : 0ull);
    }
    MaskArgs ma1, ma2, ma3, ma4;
    {
        MT19937 rng; rng.seed(0);
        auto doCall = [&](int n, int steps, MaskArgs& out) {
            for (int s = 0; s < steps; s++) {
                int scale = n - (s + 1);
                int pop = (int)Bn[n][scale];
                int r = perm_first(rng, pop);
                out.m[s] = unrank_mask(n, scale, (long long)r, Bn);
                out.inv[s] = 1.0f / (float)scale;
            }
        };
        doCall(16, 14, ma1); doCall(14, 12, ma2); doCall(8, 6, ma3); doCall(6, 4, ma4);
    }

    float *p_app, *p_motproj, *p_qproj, *p_mean, *p_objs2, *p_clip, *p_gatesx,
          *p_gates, *p_hst, *p_cst, *p_vm, *p_objs4;
    cudaGetSymbolAddress((void**)&p_app, g_app);
    cudaGetSymbolAddress((void**)&p_motproj, g_motproj);
    cudaGetSymbolAddress((void**)&p_qproj, g_qproj);
    cudaGetSymbolAddress((void**)&p_mean, g_mean);
    cudaGetSymbolAddress((void**)&p_objs2, g_objs2);
    cudaGetSymbolAddress((void**)&p_clip, g_clip);
    cudaGetSymbolAddress((void**)&p_gatesx, g_gatesx);
    cudaGetSymbolAddress((void**)&p_gates, g_gates);
    cudaGetSymbolAddress((void**)&p_hst, g_hstate);
    cudaGetSymbolAddress((void**)&p_cst, g_cstate);
    cudaGetSymbolAddress((void**)&p_vm, g_vm);
    cudaGetSymbolAddress((void**)&p_objs4, g_objs4);

    // ---- projections ----
    launch_gemm(false, qe, 512, Wq, bq, p_qproj, 128, 0, 512, 128, 512, 512, 0);
    launch_gemm(false, mot, 2048, Wm, bmv, p_motproj, 1024, 0, 512, 1024, 512, 2048, 0);
    launch_gemm(true, app, 2048, Wa, ba, p_app, 16384, 0, 512, 16384, 512, 2048, 0);
    launch_gemm(true, mot, 2048, Wih, bih, p_gatesx, 1024, 0, 2048, 1024, 2048, 2048, 0);

    // ---- crn_m: 14 steps batched, objs = g_app [1024,16,512], cond = motproj ----
    mean_subset_batched<<<dim3(512, 14), 256>>>(p_mean, p_app, 1024, 0, 16 * 512, 512, ma1, 1024);
    launch_crn(p_mean, p_motproj, 1, W1, b1, p_objs2, 512, 1024, 0, 14 * 512, 1024, 14, 1);

    // ---- crn_q: 12 gated steps batched, objs = g_objs2, cond = qproj[m/8] ----
    mean_subset_batched<<<dim3(512, 12), 256>>>(p_mean, p_objs2, 1024, 0, 14 * 512, 512, ma2, 1024);
    launch_crn(p_mean, p_qproj, 8, W2, b2, p_clip, 512, 1024, 0, 12 * 512, 1024, 12, 1);
    launch_crn(p_mean, p_qproj, 8, gW2, gb2, p_clip, 512, 1024, 0, 12 * 512, 1024, 12, 2);

    // ---- LSTM over motion (T = 8) ----
    zero_kernel<<<256, 256>>>(p_hst, 128 * 512);
    zero_kernel<<<256, 256>>>(p_cst, 128 * 512);
    for (int t = 0; t < 8; t++) {
        launch_gemm(false, p_hst, 512, Whh, bhh, p_gates, 128, 0, 2048,
                    128, 2048, 512, 3, p_gatesx + (size_t)t * 2048, 8 * 2048);
        lstm_cell_kernel<<<256, 256>>>(p_gates, p_hst, p_cst);
    }
    launch_gemm(false, p_hst, 512, Wvm, bvm, p_vm, 128, 0, 512, 128, 512, 512, 0);

    // ---- crn_vm: 6 steps batched, objs = clip [B,8,12,D], cond = vm[m/12] ----
    mean_subset_batched<<<dim3(768, 6), 256>>>(p_mean, p_clip, 12, 8 * 12 * 512, 512, 12 * 512, ma3, 1536);
    launch_crn(p_mean, p_vm, 12, W3, b3, p_objs4, 12 * 512, 12, 6 * 12 * 512, 512, 1536, 6, 1);

    // ---- crn_vq: 4 gated steps batched, objs4 [B,6,12,D] -> out [B,48,D] ----
    mean_subset_batched<<<dim3(768, 4), 256>>>(p_mean, p_objs4, 12, 6 * 12 * 512, 512, 12 * 512, ma4, 1536);
    launch_crn(p_mean, p_qproj, 12, W4, b4, outp, 12 * 512, 12, 48 * 512, 512, 1536, 4, 1);
    launch_crn(p_mean, p_qproj, 12, gW4, gb4, outp, 12 * 512, 12, 48 * 512, 512, 1536, 4, 2);
}

// round 7
// speedup vs baseline: 1.9936x; 1.9936x over previous
#include <cuda_runtime.h>
#include <cuda_bf16.h>
#include <cstdint>
#include <cstddef>
typedef __nv_bfloat16 bf16;
typedef unsigned long long u64;
typedef uint32_t u32;

__device__ __align__(256) float g_app[16384*512];
__device__ __align__(256) float g_motproj[1024*512];
__device__ __align__(256) float g_qproj[128*512];
__device__ __align__(256) float g_objs2[1024*14*512];
__device__ __align__(256) float g_clip[1024*12*512];
__device__ __align__(256) float g_gatesx[1024*2048];
__device__ __align__(256) float g_gates[128*2048];
__device__ __align__(256) float g_hstate[128*512];
__device__ __align__(256) float g_cstate[128*512];
__device__ __align__(256) float g_vm[128*512];
__device__ __align__(256) float g_objs4[128*6*12*512];
__device__ __align__(256) bf16 b_appH[16384*2048], b_appL[16384*2048];
__device__ __align__(256) bf16 b_motH[1024*2048],  b_motL[1024*2048];
__device__ __align__(256) bf16 b_WaH[512*2048],    b_WaL[512*2048];
__device__ __align__(256) bf16 b_WmH[512*2048],    b_WmL[512*2048];
__device__ __align__(256) bf16 b_WihH[2048*2048],  b_WihL[2048*2048];
__device__ __align__(256) bf16 b_W1H[15*512*1024], b_W1L[15*512*1024];
__device__ __align__(256) bf16 b_W2H[13*512*1024], b_W2L[13*512*1024];
__device__ __align__(256) bf16 b_gW2H[13*512*1024],b_gW2L[13*512*1024];
__device__ __align__(256) bf16 b_W3H[7*512*1024],  b_W3L[7*512*1024];
__device__ __align__(256) bf16 b_W4H[5*512*1024],  b_W4L[5*512*1024];
__device__ __align__(256) bf16 b_gW4H[5*512*1024], b_gW4L[5*512*1024];
__device__ __align__(256) bf16 b_catH[14336*1024], b_catL[14336*1024];

struct MaskArgs { unsigned m[14]; float inv[14]; };

static __device__ __forceinline__ u32 sm_u32(const void* p){
    u32 a; asm("{ .reg .u64 t; cvta.to.shared.u64 t, %1; cvt.u32.u64 %0, t; }":"=r"(a):"l"(p)); return a;
}
#define SW128(o) ((o) ^ (((o) >> 3) & 0x70))
static __device__ __forceinline__ void cpa(u32 s, const void* g){
    asm volatile("cp.async.cg.shared.global [%0], [%1], 16;" :: "r"(s), "l"(g) : "memory");
}
static __device__ __forceinline__ void ldm4(u32* r, u32 a){
    asm volatile("ldmatrix.sync.aligned.m8n8.x4.shared.b16 {%0,%1,%2,%3}, [%4];"
        : "=r"(r[0]),"=r"(r[1]),"=r"(r[2]),"=r"(r[3]) : "r"(a));
}
static __device__ __forceinline__ void mma_bf16(float* d, const u32* a, const u32* b){
    asm volatile("mma.sync.aligned.m16n8k16.row.col.f32.bf16.bf16.f32 "
        "{%0,%1,%2,%3}, {%4,%5,%6,%7}, {%8,%9}, {%0,%1,%2,%3};"
        : "+f"(d[0]),"+f"(d[1]),"+f"(d[2]),"+f"(d[3])
        : "r"(a[0]),"r"(a[1]),"r"(a[2]),"r"(a[3]), "r"(b[0]),"r"(b[1]));
}

// ---- tensor GEMM via mma.sync (HMMA bf16, hi/lo split, fp32 accum) ----
// C = act(A@W^T + bias); A≈Ah+Al [M,K], W≈Wh+Wl [N,K]. Tile 128x128, Ktile 64.
// act: 0 none | 1 elu | 2 C *= sigmoid(v)
__global__ void __launch_bounds__(256,1)
tgemm(const bf16* __restrict__ Ah, const bf16* __restrict__ Al, long long A_step, int lda,
      const bf16* __restrict__ Wh, const bf16* __restrict__ Wl, long long W_step,
      const float* __restrict__ bias, long long bias_step,
      float* __restrict__ C, long long C_step,
      int c_inner, long long c_so, long long c_sr, int K, int act)
{
    extern __shared__ char dsm[];
    const int tid=threadIdx.x, wid=tid>>5, lane=tid&31;
    const int wm=wid>>2, wn=wid&3;
    const int bm=blockIdx.y*128, bn=blockIdx.x*128, step=blockIdx.z;
    Ah+=(size_t)step*A_step; Al+=(size_t)step*A_step;
    Wh+=(size_t)step*W_step; Wl+=(size_t)step*W_step;
    bias+=(size_t)step*bias_step; C+=(size_t)step*C_step;
    u32 raw=sm_u32(dsm), pad=((raw+1023u)&~1023u)-raw;
    const u32 base=raw+pad;

    float acc[4][4][4];
#pragma unroll
    for(int i=0;i<4;i++)
#pragma unroll
    for(int j=0;j<4;j++)
#pragma unroll
    for(int k=0;k<4;k++) acc[i][j][k]=0.f;

    const int ntiles=K>>6;
    // prologue load stage 0
    {
        const u32 stg=base; const int k0=0;
#pragma unroll
        for(int i=0;i<4;i++){
            int q=tid+i*256, row=q>>3, c16=q&7;
            u32 so=SW128((u32)(row*128+c16*16));
            size_t ao=(size_t)(bm+row)*lda+k0+c16*8;
            size_t wo=(size_t)(bn+row)*K+k0+c16*8;
            cpa(stg+so,Ah+ao); cpa(stg+16384+so,Al+ao);
            cpa(stg+32768+so,Wh+wo); cpa(stg+49152+so,Wl+wo);
        }
        asm volatile("cp.async.commit_group;" ::: "memory");
    }
    for(int t=0;t<ntiles;t++){
        if(t+1<ntiles){
            const u32 stg=base+((t+1)&1)*65536u; const int k0=(t+1)<<6;
#pragma unroll
            for(int i=0;i<4;i++){
                int q=tid+i*256, row=q>>3, c16=q&7;
                u32 so=SW128((u32)(row*128+c16*16));
                size_t ao=(size_t)(bm+row)*lda+k0+c16*8;
                size_t wo=(size_t)(bn+row)*K+k0+c16*8;
                cpa(stg+so,Ah+ao); cpa(stg+16384+so,Al+ao);
                cpa(stg+32768+so,Wh+wo); cpa(stg+49152+so,Wl+wo);
            }
            asm volatile("cp.async.commit_group;" ::: "memory");
            asm volatile("cp.async.wait_group 1;" ::: "memory");
        } else {
            asm volatile("cp.async.wait_group 0;" ::: "memory");
        }
        __syncthreads();
        const u32 stg=base+(t&1)*65536u;
        const int sub=lane>>3, l7=lane&7;
        const int arow=(sub&1)*8+l7, akb=(sub>>1)*16;
        const int brow=(sub>>1)*8+l7, bkb=(sub&1)*16;
#pragma unroll
        for(int ks=0;ks<4;ks++){
            u32 ar[2][4][4];
#pragma unroll
            for(int mt=0;mt<4;mt++){
                int row=wm*64+mt*16+arow;
                u32 so=SW128((u32)(row*128+ks*32+akb));
                ldm4(ar[0][mt], stg+so);
                ldm4(ar[1][mt], stg+16384+so);
            }
            u32 br[2][2][4];
#pragma unroll
            for(int p=0;p<2;p++){
                int row=wn*32+p*16+brow;
                u32 so=SW128((u32)(row*128+ks*32+bkb));
                ldm4(br[0][p], stg+32768+so);
                ldm4(br[1][p], stg+49152+so);
            }
#pragma unroll
            for(int mt=0;mt<4;mt++)
#pragma unroll
            for(int nt=0;nt<4;nt++){
                int p=nt>>1, h=(nt&1)*2;
                mma_bf16(acc[mt][nt], ar[0][mt], &br[0][p][h]);  // hh
                mma_bf16(acc[mt][nt], ar[0][mt], &br[1][p][h]);  // hl
                mma_bf16(acc[mt][nt], ar[1][mt], &br[0][p][h]);  // lh
            }
        }
        __syncthreads();
    }
    // epilogue
#pragma unroll
    for(int mt=0;mt<4;mt++){
        int mrow=bm+wm*64+mt*16+(lane>>2);
#pragma unroll
        for(int hf=0;hf<2;hf++){
            int m=mrow+hf*8;
            size_t crow=(size_t)(m/c_inner)*(size_t)c_so+(size_t)(m%c_inner)*(size_t)c_sr;
#pragma unroll
            for(int nt=0;nt<4;nt++){
                int n=bn+wn*32+nt*8+(lane&3)*2;
                float v0=acc[mt][nt][hf*2+0]+bias[n];
                float v1=acc[mt][nt][hf*2+1]+bias[n+1];
                float* cp0=C+crow+n;
                if(act==0){ cp0[0]=v0; cp0[1]=v1; }
                else if(act==1){
                    cp0[0]=(v0>0.f)?v0:expm1f(v0);
                    cp0[1]=(v1>0.f)?v1:expm1f(v1);
                } else {
                    cp0[0]*=1.f/(1.f+expf(-v0));
                    cp0[1]*=1.f/(1.f+expf(-v1));
                }
            }
        }
    }
}

__global__ void split_bf16(const float* __restrict__ s, bf16* __restrict__ h, bf16* __restrict__ l, int n){
    int i=(blockIdx.x*blockDim.x+threadIdx.x)*4;
    if(i>=n) return;
    float4 v=*(const float4*)(s+i); float a[4]={v.x,v.y,v.z,v.w};
#pragma unroll
    for(int j=0;j<4;j++){ bf16 hb=__float2bfloat16(a[j]); h[i+j]=hb; l[i+j]=__float2bfloat16(a[j]-__bfloat162float(hb)); }
}
__global__ void mean_subset_bf16(bf16* __restrict__ h, bf16* __restrict__ l,
    const float* __restrict__ objs, int inner, long long sB, long long sR, long long sJ,
    MaskArgs ma, int M){
    int step=blockIdx.y, idx=blockIdx.x*blockDim.x+threadIdx.x;
    int m=idx>>7, d4=(idx&127)<<2;
    if(m>=M) return;
    unsigned mm=ma.m[step]; float inv=ma.inv[step];
    const float* bp=objs+(size_t)(m/inner)*sB+(size_t)(m%inner)*sR+d4;
    float s0=0,s1=0,s2=0,s3=0;
    while(mm){ int j=__ffs((int)mm)-1; mm&=mm-1;
        float4 v=*(const float4*)(bp+(size_t)j*sJ); s0+=v.x;s1+=v.y;s2+=v.z;s3+=v.w; }
    float a[4]={s0*inv,s1*inv,s2*inv,s3*inv};
    size_t o=((size_t)step*M+m)*1024+d4;
#pragma unroll
    for(int j=0;j<4;j++){ bf16 hb=__float2bfloat16(a[j]); h[o+j]=hb; l[o+j]=__float2bfloat16(a[j]-__bfloat162float(hb)); }
}
__global__ void cond_fill_bf16(bf16* __restrict__ h, bf16* __restrict__ l,
    const float* __restrict__ cond, int div, int M){
    int step=blockIdx.y, idx=blockIdx.x*blockDim.x+threadIdx.x;
    int m=idx>>7, d4=(idx&127)<<2;
    if(m>=M) return;
    float4 v=*(const float4*)(cond+(size_t)(m/div)*512+d4);
    float a[4]={v.x,v.y,v.z,v.w};
    size_t o=((size_t)step*M+m)*1024+512+d4;
#pragma unroll
    for(int j=0;j<4;j++){ bf16 hb=__float2bfloat16(a[j]); h[o+j]=hb; l[o+j]=__float2bfloat16(a[j]-__bfloat162float(hb)); }
}
__global__ void zero_kernel(float* p, int n){
    int i=blockIdx.x*blockDim.x+threadIdx.x; if(i<n) p[i]=0.f;
}
__global__ void lstm_cell_kernel(const float* __restrict__ g, float* __restrict__ h, float* __restrict__ c){
    int idx=blockIdx.x*blockDim.x+threadIdx.x;
    int m=idx>>9, d=idx&511;
    const float* gr=g+(size_t)m*2048;
    float ig=1.f/(1.f+expf(-gr[d])), fg=1.f/(1.f+expf(-gr[512+d]));
    float gg=tanhf(gr[1024+d]), og=1.f/(1.f+expf(-gr[1536+d]));
    float cn=fg*c[idx]+ig*gg;
    c[idx]=cn; h[idx]=og*tanhf(cn);
}
// ---- SIMT small GEMM (qproj/LSTM/vm); act: 0 none | 3 +=add ----
__global__ void __launch_bounds__(256)
sgemm_small(const float* __restrict__ A, int lda, const float* __restrict__ W,
            const float* __restrict__ bias, const float* __restrict__ add, long long add_sr,
            float* __restrict__ C, long long c_sr, int K, int act)
{
    constexpr int BM=64, BK=16;
    __shared__ __align__(16) float As[BK][BM];
    __shared__ __align__(16) float Bs[BK][BM];
    const int bm=blockIdx.y*BM, bn=blockIdx.x*BM;
    const int tid=threadIdx.x, tx=tid&15, ty=tid>>4;
    u64 acc[4][2];
#pragma unroll
    for(int i=0;i<4;i++){acc[i][0]=0ull;acc[i][1]=0ull;}
    for(int k0=0;k0<K;k0+=BK){
        { int r=tid>>2, c4=(tid&3)<<2;
          float4 va=*(const float4*)(A+(size_t)(bm+r)*lda+k0+c4);
          As[c4+0][r]=va.x;As[c4+1][r]=va.y;As[c4+2][r]=va.z;As[c4+3][r]=va.w;
          float4 vb=*(const float4*)(W+(size_t)(bn+r)*K+k0+c4);
          Bs[c4+0][r]=vb.x;Bs[c4+1][r]=vb.y;Bs[c4+2][r]=vb.z;Bs[c4+3][r]=vb.w; }
        __syncthreads();
#pragma unroll
        for(int kk=0;kk<BK;kk++){
            float4 a0=*(const float4*)(&As[kk][ty*4]);
            float av[4]={a0.x,a0.y,a0.z,a0.w};
            double2 b0=*(const double2*)(&Bs[kk][tx*4]);
            u64 bp[2]={(u64)__double_as_longlong(b0.x),(u64)__double_as_longlong(b0.y)};
#pragma unroll
            for(int i=0;i<4;i++){
                u64 ap; asm("mov.b64 %0, {%1, %1};":"=l"(ap):"r"(__float_as_uint(av[i])));
                asm("fma.rn.f32x2 %0, %1, %2, %0;":"+l"(acc[i][0]):"l"(ap),"l"(bp[0]));
                asm("fma.rn.f32x2 %0, %1, %2, %0;":"+l"(acc[i][1]):"l"(ap),"l"(bp[1]));
            }
        }
        __syncthreads();
    }
#pragma unroll
    for(int i=0;i<4;i++){
        int m=bm+ty*4+i;
#pragma unroll
        for(int j=0;j<4;j++){
            int n=bn+tx*4+j;
            u64 pk=acc[i][j>>1];
            unsigned lv=(j&1)?(unsigned)(pk>>32):(unsigned)pk;
            float v=__uint_as_float(lv)+bias[n];
            if(act==3) v+=add[(size_t)m*add_sr+n];
            C[(size_t)m*c_sr+n]=v;
        }
    }
}

namespace {
struct MT19937 {
    unsigned mt[624]; int pos;
    void seed(unsigned s){ for(int i=0;i<624;i++){mt[i]=s; s=1812433253u*(s^(s>>30))+(unsigned)i+1u;} pos=624; }
    unsigned next(){
        if(pos>=624){ for(int i=0;i<624;i++){
            unsigned y=(mt[i]&0x80000000u)|(mt[(i+1)%624]&0x7fffffffu);
            unsigned v=mt[(i+397)%624]^(y>>1); if(y&1u)v^=0x9908b0dfu; mt[i]=v; } pos=0; }
        unsigned y=mt[pos++];
        y^=y>>11; y^=(y<<7)&0x9d2c5680u; y^=(y<<15)&0xefc60000u; y^=y>>18; return y;
    }
    unsigned interval(unsigned mx){
        if(!mx) return 0;
        unsigned m=mx; m|=m>>1;m|=m>>2;m|=m>>4;m|=m>>8;m|=m>>16;
        unsigned v; do{v=next()&m;}while(v>mx); return v;
    }
};
static int perm_first(MT19937& r,int n){
    static int arr[13000];
    for(int i=0;i<n;i++)arr[i]=i;
    for(int i=n-1;i>0;i--){int j=(int)r.interval((unsigned)i);int t=arr[i];arr[i]=arr[j];arr[j]=t;}
    return arr[0];
}
static unsigned unrank_mask(int n,int k,long long idx,const u64 Bn[17][17]){
    unsigned mask=0;int x=0;
    for(int i=0;i<k;i++) for(int v=x;;v++){
        long long c=(long long)Bn[n-1-v][k-1-i];
        if(idx<c){mask|=1u<<v;x=v+1;break;} idx-=c; }
    return mask;
}
constexpr size_t TG_SMEM = 2*65536 + 1024;
static void launch_t(const bf16* Ah,const bf16* Al,long long A_step,int lda,
                     const bf16* Wh,const bf16* Wl,long long W_step,
                     const float* bias,long long bias_step,
                     float* C,long long C_step,int c_inner,long long c_so,long long c_sr,
                     int M,int N,int K,int steps,int act){
    dim3 g(N/128, M/128, steps);
    tgemm<<<g,256,TG_SMEM>>>(Ah,Al,A_step,lda,Wh,Wl,W_step,bias,bias_step,C,C_step,c_inner,c_so,c_sr,K,act);
}
static void split(const float* s, bf16* h, bf16* l, int n){ split_bf16<<<(n/4+255)/256,256>>>(s,h,l,n); }
template<typename T> static T* sym(T* s){ void* p; cudaGetSymbolAddress(&p,(const void*)s); return (T*)p; }
}

extern "C" void kernel_launch(void* const* d_in, const int* in_sizes, int n_in,
                              void* d_out, int out_size)
{
    (void)in_sizes;(void)n_in;(void)out_size;
    const float* app=(const float*)d_in[0]; const float* mot=(const float*)d_in[1];
    const float* qe=(const float*)d_in[2];  const float* Wq=(const float*)d_in[3];
    const float* bq=(const float*)d_in[4];  const float* Wm=(const float*)d_in[5];
    const float* bmv=(const float*)d_in[6]; const float* Wa=(const float*)d_in[7];
    const float* ba=(const float*)d_in[8];  const float* Wvm=(const float*)d_in[9];
    const float* bvm=(const float*)d_in[10];const float* Wih=(const float*)d_in[11];
    const float* Whh=(const float*)d_in[12];const float* bih=(const float*)d_in[13];
    const float* bhh=(const float*)d_in[14];const float* W1=(const float*)d_in[15];
    const float* b1=(const float*)d_in[16]; const float* W2=(const float*)d_in[17];
    const float* b2=(const float*)d_in[18]; const float* gW2=(const float*)d_in[19];
    const float* gb2=(const float*)d_in[20];const float* W3=(const float*)d_in[21];
    const float* b3=(const float*)d_in[22]; const float* W4=(const float*)d_in[23];
    const float* b4=(const float*)d_in[24]; const float* gW4=(const float*)d_in[25];
    const float* gb4=(const float*)d_in[26];
    float* outp=(float*)d_out;

    cudaFuncSetAttribute(tgemm, cudaFuncAttributeMaxDynamicSharedMemorySize, (int)TG_SMEM);

    u64 Bn[17][17]={};
    for(int i=0;i<=16;i++){ Bn[i][0]=1;
        for(int j=1;j<=i;j++) Bn[i][j]=Bn[i-1][j-1]+((j<=i-1)?Bn[i-1][j]:0ull); }
    MaskArgs ma1,ma2,ma3,ma4;
    {
        MT19937 rng; rng.seed(0);
        auto doCall=[&](int n,int steps,MaskArgs& o){
            for(int s=0;s<steps;s++){
                int scale=n-(s+1); int pop=(int)Bn[n][scale];
                int r=perm_first(rng,pop);
                o.m[s]=unrank_mask(n,scale,(long long)r,Bn);
                o.inv[s]=1.0f/(float)scale;
            }
        };
        doCall(16,14,ma1); doCall(14,12,ma2); doCall(8,6,ma3); doCall(6,4,ma4);
    }

    float *p_app=sym(g_app),*p_motproj=sym(g_motproj),*p_qproj=sym(g_qproj),
          *p_objs2=sym(g_objs2),*p_clip=sym(g_clip),*p_gatesx=sym(g_gatesx),
          *p_gates=sym(g_gates),*p_hst=sym(g_hstate),*p_cst=sym(g_cstate),
          *p_vm=sym(g_vm),*p_objs4=sym(g_objs4);
    bf16 *appH=sym(b_appH),*appL=sym(b_appL),*motH=sym(b_motH),*motL=sym(b_motL),
         *WaH=sym(b_WaH),*WaL=sym(b_WaL),*WmH=sym(b_WmH),*WmL=sym(b_WmL),
         *WihH=sym(b_WihH),*WihL=sym(b_WihL),
         *W1H=sym(b_W1H),*W1L=sym(b_W1L),*W2H=sym(b_W2H),*W2L=sym(b_W2L),
         *gW2H=sym(b_gW2H),*gW2L=sym(b_gW2L),*W3H=sym(b_W3H),*W3L=sym(b_W3L),
         *W4H=sym(b_W4H),*W4L=sym(b_W4L),*gW4H=sym(b_gW4H),*gW4L=sym(b_gW4L),
         *catH=sym(b_catH),*catL=sym(b_catL);

    split(app,appH,appL,16384*2048); split(mot,motH,motL,1024*2048);
    split(Wa,WaH,WaL,512*2048); split(Wm,WmH,WmL,512*2048);
    split(Wih,WihH,WihL,2048*2048);
    split(W1,W1H,W1L,15*512*1024); split(W2,W2H,W2L,13*512*1024);
    split(gW2,gW2H,gW2L,13*512*1024); split(W3,W3H,W3L,7*512*1024);
    split(W4,W4H,W4L,5*512*1024); split(gW4,gW4H,gW4L,5*512*1024);

    { dim3 g(8,2); sgemm_small<<<g,256>>>(qe,512,Wq,bq,nullptr,0,p_qproj,512,512,0); }
    launch_t(motH,motL,0,2048, WmH,WmL,0, bmv,0, p_motproj,0, 1024,0,512, 1024,512,2048,1,0);
    launch_t(appH,appL,0,2048, WaH,WaL,0, ba,0,  p_app,0,     16384,0,512,16384,512,2048,1,0);
    launch_t(motH,motL,0,2048, WihH,WihL,0, bih,0, p_gatesx,0, 1024,0,2048,1024,2048,2048,1,0);

    const long long WS=512*1024;
    // crn_m: 14 steps
    mean_subset_bf16<<<dim3(512,14),256>>>(catH,catL,p_app,1024,0,16*512,512,ma1,1024);
    cond_fill_bf16<<<dim3(512,14),256>>>(catH,catL,p_motproj,1,1024);
    launch_t(catH,catL,1024LL*1024,1024, W1H+WS,W1L+WS,WS, b1+512,512,
             p_objs2,512, 1024,0,14*512, 1024,512,1024,14,1);
    // crn_q: 12 gated steps
    mean_subset_bf16<<<dim3(512,12),256>>>(catH,catL,p_objs2,1024,0,14*512,512,ma2,1024);
    cond_fill_bf16<<<dim3(512,12),256>>>(catH,catL,p_qproj,8,1024);
    launch_t(catH,catL,1024LL*1024,1024, W2H+WS,W2L+WS,WS, b2+512,512,
             p_clip,512, 1024,0,12*512, 1024,512,1024,12,1);
    launch_t(catH,catL,1024LL*1024,1024, gW2H+WS,gW2L+WS,WS, gb2+512,512,
             p_clip,512, 1024,0,12*512, 1024,512,1024,12,2);
    // LSTM
    zero_kernel<<<256,256>>>(p_hst,128*512);
    zero_kernel<<<256,256>>>(p_cst,128*512);
    for(int t=0;t<8;t++){
        dim3 g(32,2);
        sgemm_small<<<g,256>>>(p_hst,512,Whh,bhh,p_gatesx+(size_t)t*2048,8*2048,p_gates,2048,512,3);
        lstm_cell_kernel<<<256,256>>>(p_gates,p_hst,p_cst);
    }
    { dim3 g(8,2); sgemm_small<<<g,256>>>(p_hst,512,Wvm,bvm,nullptr,0,p_vm,512,512,0); }
    // crn_vm: 6 steps
    mean_subset_bf16<<<dim3(768,6),256>>>(catH,catL,p_clip,12,8*12*512,512,12*512,ma3,1536);
    cond_fill_bf16<<<dim3(768,6),256>>>(catH,catL,p_vm,12,1536);
    launch_t(catH,catL,1536LL*1024,1024, W3H+WS,W3L+WS,WS, b3+512,512,
             p_objs4,12*512, 12,6*12*512,512, 1536,512,1024,6,1);
    // crn_vq: 4 gated steps -> out
    mean_subset_bf16<<<dim3(768,4),256>>>(catH,catL,p_objs4,12,6*12*512,512,12*512,ma4,1536);
    cond_fill_bf16<<<dim3(768,4),256>>>(catH,catL,p_qproj,12,1536);
    launch_t(catH,catL,1536LL*1024,1024, W4H+WS,W4L+WS,WS, b4+512,512,
             outp,12*512, 12,48*512,512, 1536,512,1024,4,1);
    launch_t(catH,catL,1536LL*1024,1024, gW4H+WS,gW4L+WS,WS, gb4+512,512,
             outp,12*512, 12,48*512,512, 1536,512,1024,4,2);
}

// round 8
// speedup vs baseline: 2.1422x; 1.0745x over previous
#include <cuda_runtime.h>
#include <cuda_bf16.h>
#include <cstdint>
#include <cstddef>
typedef __nv_bfloat16 bf16;
typedef unsigned long long u64;
typedef uint32_t u32;

__device__ __align__(256) float g_app[16384*512];
__device__ __align__(256) float g_motproj[1024*512];
__device__ __align__(256) float g_qproj[128*512];
__device__ __align__(256) float g_objs2[1024*14*512];
__device__ __align__(256) float g_clip[1024*12*512];
__device__ __align__(256) float g_gatesx[1024*2048];
__device__ __align__(256) float g_gates[128*2048];
__device__ __align__(256) float g_hstate[128*512];
__device__ __align__(256) float g_cstate[128*512];
__device__ __align__(256) float g_vm[128*512];
__device__ __align__(256) float g_objs4[128*6*12*512];
__device__ __align__(256) bf16 b_appH[16384*2048], b_appL[16384*2048];
__device__ __align__(256) bf16 b_motH[1024*2048],  b_motL[1024*2048];
__device__ __align__(256) bf16 b_WaH[512*2048],    b_WaL[512*2048];
__device__ __align__(256) bf16 b_WmH[512*2048],    b_WmL[512*2048];
__device__ __align__(256) bf16 b_WihH[2048*2048],  b_WihL[2048*2048];
__device__ __align__(256) bf16 b_W1H[15*512*1024], b_W1L[15*512*1024];
__device__ __align__(256) bf16 b_W2H[13*512*1024], b_W2L[13*512*1024];
__device__ __align__(256) bf16 b_gW2H[13*512*1024],b_gW2L[13*512*1024];
__device__ __align__(256) bf16 b_W3H[7*512*1024],  b_W3L[7*512*1024];
__device__ __align__(256) bf16 b_W4H[5*512*1024],  b_W4L[5*512*1024];
__device__ __align__(256) bf16 b_gW4H[5*512*1024], b_gW4L[5*512*1024];
__device__ __align__(256) bf16 b_catH[14336*1024], b_catL[14336*1024];

struct MaskArgs { unsigned m[14]; float inv[14]; };

static __device__ __forceinline__ u32 sm_u32(const void* p){
    u32 a; asm("{ .reg .u64 t; cvta.to.shared.u64 t, %1; cvt.u32.u64 %0, t; }":"=r"(a):"l"(p)); return a;
}
#define SW128(o) ((o) ^ (((o) >> 3) & 0x70))
static __device__ __forceinline__ void cpa(u32 s, const void* g){
    asm volatile("cp.async.cg.shared.global [%0], [%1], 16;" :: "r"(s), "l"(g) : "memory");
}
static __device__ __forceinline__ void ldm4(u32* r, u32 a){
    asm volatile("ldmatrix.sync.aligned.m8n8.x4.shared.b16 {%0,%1,%2,%3}, [%4];"
        : "=r"(r[0]),"=r"(r[1]),"=r"(r[2]),"=r"(r[3]) : "r"(a));
}
static __device__ __forceinline__ void mma_bf16(float* d, const u32* a, const u32* b){
    asm volatile("mma.sync.aligned.m16n8k16.row.col.f32.bf16.bf16.f32 "
        "{%0,%1,%2,%3}, {%4,%5,%6,%7}, {%8,%9}, {%0,%1,%2,%3};"
        : "+f"(d[0]),"+f"(d[1]),"+f"(d[2]),"+f"(d[3])
        : "r"(a[0]),"r"(a[1]),"r"(a[2]),"r"(a[3]), "r"(b[0]),"r"(b[1]));
}
// pack 4 floats -> hi uint2 (4 bf16) and lo uint2 (4 bf16 residuals)
static __device__ __forceinline__ void pack_hl(const float* a, uint2& H, uint2& L){
    bf16 h0=__float2bfloat16(a[0]), h1=__float2bfloat16(a[1]);
    bf16 h2=__float2bfloat16(a[2]), h3=__float2bfloat16(a[3]);
    __nv_bfloat162 hp0(h0,h1), hp1(h2,h3);
    H.x=*(u32*)&hp0; H.y=*(u32*)&hp1;
    bf16 l0=__float2bfloat16(a[0]-__bfloat162float(h0));
    bf16 l1=__float2bfloat16(a[1]-__bfloat162float(h1));
    bf16 l2=__float2bfloat16(a[2]-__bfloat162float(h2));
    bf16 l3=__float2bfloat16(a[3]-__bfloat162float(h3));
    __nv_bfloat162 lp0(l0,l1), lp1(l2,l3);
    L.x=*(u32*)&lp0; L.y=*(u32*)&lp1;
}

// ---- tensor GEMM via mma.sync (HMMA bf16, hi/lo split, fp32 accum) ----
__global__ void __launch_bounds__(256,1)
tgemm(const bf16* __restrict__ Ah, const bf16* __restrict__ Al, long long A_step, int lda,
      const bf16* __restrict__ Wh, const bf16* __restrict__ Wl, long long W_step,
      const float* __restrict__ bias, long long bias_step,
      float* __restrict__ C, long long C_step,
      int c_inner, long long c_so, long long c_sr, int K, int act)
{
    extern __shared__ char dsm[];
    const int tid=threadIdx.x, wid=tid>>5, lane=tid&31;
    const int wm=wid>>2, wn=wid&3;
    const int bm=blockIdx.y*128, bn=blockIdx.x*128, step=blockIdx.z;
    Ah+=(size_t)step*A_step; Al+=(size_t)step*A_step;
    Wh+=(size_t)step*W_step; Wl+=(size_t)step*W_step;
    bias+=(size_t)step*bias_step; C+=(size_t)step*C_step;
    u32 raw=sm_u32(dsm), pad=((raw+1023u)&~1023u)-raw;
    const u32 base=raw+pad;

    float acc[4][4][4];
#pragma unroll
    for(int i=0;i<4;i++)
#pragma unroll
    for(int j=0;j<4;j++)
#pragma unroll
    for(int k=0;k<4;k++) acc[i][j][k]=0.f;

    const int ntiles=K>>6;
    {
        const u32 stg=base; const int k0=0;
#pragma unroll
        for(int i=0;i<4;i++){
            int q=tid+i*256, row=q>>3, c16=q&7;
            u32 so=SW128((u32)(row*128+c16*16));
            size_t ao=(size_t)(bm+row)*lda+k0+c16*8;
            size_t wo=(size_t)(bn+row)*K+k0+c16*8;
            cpa(stg+so,Ah+ao); cpa(stg+16384+so,Al+ao);
            cpa(stg+32768+so,Wh+wo); cpa(stg+49152+so,Wl+wo);
        }
        asm volatile("cp.async.commit_group;" ::: "memory");
    }
    for(int t=0;t<ntiles;t++){
        if(t+1<ntiles){
            const u32 stg=base+((t+1)&1)*65536u; const int k0=(t+1)<<6;
#pragma unroll
            for(int i=0;i<4;i++){
                int q=tid+i*256, row=q>>3, c16=q&7;
                u32 so=SW128((u32)(row*128+c16*16));
                size_t ao=(size_t)(bm+row)*lda+k0+c16*8;
                size_t wo=(size_t)(bn+row)*K+k0+c16*8;
                cpa(stg+so,Ah+ao); cpa(stg+16384+so,Al+ao);
                cpa(stg+32768+so,Wh+wo); cpa(stg+49152+so,Wl+wo);
            }
            asm volatile("cp.async.commit_group;" ::: "memory");
            asm volatile("cp.async.wait_group 1;" ::: "memory");
        } else {
            asm volatile("cp.async.wait_group 0;" ::: "memory");
        }
        __syncthreads();
        const u32 stg=base+(t&1)*65536u;
        const int sub=lane>>3, l7=lane&7;
        const int arow=(sub&1)*8+l7, akb=(sub>>1)*16;
        const int brow=(sub>>1)*8+l7, bkb=(sub&1)*16;
#pragma unroll
        for(int ks=0;ks<4;ks++){
            u32 ar[2][4][4];
#pragma unroll
            for(int mt=0;mt<4;mt++){
                int row=wm*64+mt*16+arow;
                u32 so=SW128((u32)(row*128+ks*32+akb));
                ldm4(ar[0][mt], stg+so);
                ldm4(ar[1][mt], stg+16384+so);
            }
            u32 br[2][2][4];
#pragma unroll
            for(int p=0;p<2;p++){
                int row=wn*32+p*16+brow;
                u32 so=SW128((u32)(row*128+ks*32+bkb));
                ldm4(br[0][p], stg+32768+so);
                ldm4(br[1][p], stg+49152+so);
            }
#pragma unroll
            for(int mt=0;mt<4;mt++)
#pragma unroll
            for(int nt=0;nt<4;nt++){
                int p=nt>>1, h=(nt&1)*2;
                mma_bf16(acc[mt][nt], ar[0][mt], &br[0][p][h]);
                mma_bf16(acc[mt][nt], ar[0][mt], &br[1][p][h]);
                mma_bf16(acc[mt][nt], ar[1][mt], &br[0][p][h]);
            }
        }
        __syncthreads();
    }
#pragma unroll
    for(int mt=0;mt<4;mt++){
        int mrow=bm+wm*64+mt*16+(lane>>2);
#pragma unroll
        for(int hf=0;hf<2;hf++){
            int m=mrow+hf*8;
            size_t crow=(size_t)(m/c_inner)*(size_t)c_so+(size_t)(m%c_inner)*(size_t)c_sr;
#pragma unroll
            for(int nt=0;nt<4;nt++){
                int n=bn+wn*32+nt*8+(lane&3)*2;
                float v0=acc[mt][nt][hf*2+0]+bias[n];
                float v1=acc[mt][nt][hf*2+1]+bias[n+1];
                float* cp0=C+crow+n;
                if(act==0){ cp0[0]=v0; cp0[1]=v1; }
                else if(act==1){
                    cp0[0]=(v0>0.f)?v0:expm1f(v0);
                    cp0[1]=(v1>0.f)?v1:expm1f(v1);
                } else {
                    cp0[0]*=1.f/(1.f+expf(-v0));
                    cp0[1]*=1.f/(1.f+expf(-v1));
                }
            }
        }
    }
}

// ---- vectorized fp32 -> bf16 hi/lo split: 16B read, 2x8B writes ----
__global__ void split_bf16(const float4* __restrict__ s, uint2* __restrict__ h,
                           uint2* __restrict__ l, int n4){
    int i=blockIdx.x*blockDim.x+threadIdx.x;
    if(i>=n4) return;
    float4 v=s[i]; float a[4]={v.x,v.y,v.z,v.w};
    uint2 H,L; pack_hl(a,H,L);
    h[i]=H; l[i]=L;
}
__global__ void mean_subset_bf16(uint2* __restrict__ h, uint2* __restrict__ l,
    const float* __restrict__ objs, int inner, long long sB, long long sR, long long sJ,
    MaskArgs ma, int M){
    int step=blockIdx.y, idx=blockIdx.x*blockDim.x+threadIdx.x;
    int m=idx>>7, d4=(idx&127)<<2;
    if(m>=M) return;
    unsigned mm=ma.m[step]; float inv=ma.inv[step];
    const float* bp=objs+(size_t)(m/inner)*sB+(size_t)(m%inner)*sR+d4;
    float s0=0,s1=0,s2=0,s3=0;
    while(mm){ int j=__ffs((int)mm)-1; mm&=mm-1;
        float4 v=*(const float4*)(bp+(size_t)j*sJ); s0+=v.x;s1+=v.y;s2+=v.z;s3+=v.w; }
    float a[4]={s0*inv,s1*inv,s2*inv,s3*inv};
    uint2 H,L; pack_hl(a,H,L);
    size_t o=(((size_t)step*M+m)*1024+d4)>>2;   // uint2 index (4 bf16 per uint2)
    h[o]=H; l[o]=L;
}
__global__ void cond_fill_bf16(uint2* __restrict__ h, uint2* __restrict__ l,
    const float* __restrict__ cond, int div, int M){
    int step=blockIdx.y, idx=blockIdx.x*blockDim.x+threadIdx.x;
    int m=idx>>7, d4=(idx&127)<<2;
    if(m>=M) return;
    float4 v=*(const float4*)(cond+(size_t)(m/div)*512+d4);
    float a[4]={v.x,v.y,v.z,v.w};
    uint2 H,L; pack_hl(a,H,L);
    size_t o=(((size_t)step*M+m)*1024+512+d4)>>2;
    h[o]=H; l[o]=L;
}
__global__ void zero_kernel(float* p, int n){
    int i=blockIdx.x*blockDim.x+threadIdx.x; if(i<n) p[i]=0.f;
}
__global__ void lstm_cell_kernel(const float* __restrict__ g, float* __restrict__ h, float* __restrict__ c){
    int idx=blockIdx.x*blockDim.x+threadIdx.x;
    int m=idx>>9, d=idx&511;
    const float* gr=g+(size_t)m*2048;
    float ig=1.f/(1.f+expf(-gr[d])), fg=1.f/(1.f+expf(-gr[512+d]));
    float gg=tanhf(gr[1024+d]), og=1.f/(1.f+expf(-gr[1536+d]));
    float cn=fg*c[idx]+ig*gg;
    c[idx]=cn; h[idx]=og*tanhf(cn);
}
// ---- SIMT small GEMM (qproj/LSTM/vm); act: 0 none | 3 +=add ----
__global__ void __launch_bounds__(256)
sgemm_small(const float* __restrict__ A, int lda, const float* __restrict__ W,
            const float* __restrict__ bias, const float* __restrict__ add, long long add_sr,
            float* __restrict__ C, long long c_sr, int K, int act)
{
    constexpr int BM=64, BK=16;
    __shared__ __align__(16) float As[BK][BM];
    __shared__ __align__(16) float Bs[BK][BM];
    const int bm=blockIdx.y*BM, bn=blockIdx.x*BM;
    const int tid=threadIdx.x, tx=tid&15, ty=tid>>4;
    u64 acc[4][2];
#pragma unroll
    for(int i=0;i<4;i++){acc[i][0]=0ull;acc[i][1]=0ull;}
    for(int k0=0;k0<K;k0+=BK){
        { int r=tid>>2, c4=(tid&3)<<2;
          float4 va=*(const float4*)(A+(size_t)(bm+r)*lda+k0+c4);
          As[c4+0][r]=va.x;As[c4+1][r]=va.y;As[c4+2][r]=va.z;As[c4+3][r]=va.w;
          float4 vb=*(const float4*)(W+(size_t)(bn+r)*K+k0+c4);
          Bs[c4+0][r]=vb.x;Bs[c4+1][r]=vb.y;Bs[c4+2][r]=vb.z;Bs[c4+3][r]=vb.w; }
        __syncthreads();
#pragma unroll
        for(int kk=0;kk<BK;kk++){
            float4 a0=*(const float4*)(&As[kk][ty*4]);
            float av[4]={a0.x,a0.y,a0.z,a0.w};
            double2 b0=*(const double2*)(&Bs[kk][tx*4]);
            u64 bp[2]={(u64)__double_as_longlong(b0.x),(u64)__double_as_longlong(b0.y)};
#pragma unroll
            for(int i=0;i<4;i++){
                u64 ap; asm("mov.b64 %0, {%1, %1};":"=l"(ap):"r"(__float_as_uint(av[i])));
                asm("fma.rn.f32x2 %0, %1, %2, %0;":"+l"(acc[i][0]):"l"(ap),"l"(bp[0]));
                asm("fma.rn.f32x2 %0, %1, %2, %0;":"+l"(acc[i][1]):"l"(ap),"l"(bp[1]));
            }
        }
        __syncthreads();
    }
#pragma unroll
    for(int i=0;i<4;i++){
        int m=bm+ty*4+i;
#pragma unroll
        for(int j=0;j<4;j++){
            int n=bn+tx*4+j;
            u64 pk=acc[i][j>>1];
            unsigned lv=(j&1)?(unsigned)(pk>>32):(unsigned)pk;
            float v=__uint_as_float(lv)+bias[n];
            if(act==3) v+=add[(size_t)m*add_sr+n];
            C[(size_t)m*c_sr+n]=v;
        }
    }
}

namespace {
struct MT19937 {
    unsigned mt[624]; int pos;
    void seed(unsigned s){ for(int i=0;i<624;i++){mt[i]=s; s=1812433253u*(s^(s>>30))+(unsigned)i+1u;} pos=624; }
    unsigned next(){
        if(pos>=624){ for(int i=0;i<624;i++){
            unsigned y=(mt[i]&0x80000000u)|(mt[(i+1)%624]&0x7fffffffu);
            unsigned v=mt[(i+397)%624]^(y>>1); if(y&1u)v^=0x9908b0dfu; mt[i]=v; } pos=0; }
        unsigned y=mt[pos++];
        y^=y>>11; y^=(y<<7)&0x9d2c5680u; y^=(y<<15)&0xefc60000u; y^=y>>18; return y;
    }
    unsigned interval(unsigned mx){
        if(!mx) return 0;
        unsigned m=mx; m|=m>>1;m|=m>>2;m|=m>>4;m|=m>>8;m|=m>>16;
        unsigned v; do{v=next()&m;}while(v>mx); return v;
    }
};
static int perm_first(MT19937& r,int n){
    static int arr[13000];
    for(int i=0;i<n;i++)arr[i]=i;
    for(int i=n-1;i>0;i--){int j=(int)r.interval((unsigned)i);int t=arr[i];arr[i]=arr[j];arr[j]=t;}
    return arr[0];
}
static unsigned unrank_mask(int n,int k,long long idx,const u64 Bn[17][17]){
    unsigned mask=0;int x=0;
    for(int i=0;i<k;i++) for(int v=x;;v++){
        long long c=(long long)Bn[n-1-v][k-1-i];
        if(idx<c){mask|=1u<<v;x=v+1;break;} idx-=c; }
    return mask;
}
constexpr size_t TG_SMEM = 2*65536 + 1024;
static void launch_t(const bf16* Ah,const bf16* Al,long long A_step,int lda,
                     const bf16* Wh,const bf16* Wl,long long W_step,
                     const float* bias,long long bias_step,
                     float* C,long long C_step,int c_inner,long long c_so,long long c_sr,
                     int M,int N,int K,int steps,int act){
    dim3 g(N/128, M/128, steps);
    tgemm<<<g,256,TG_SMEM>>>(Ah,Al,A_step,lda,Wh,Wl,W_step,bias,bias_step,C,C_step,c_inner,c_so,c_sr,K,act);
}
static void split(const float* s, bf16* h, bf16* l, int n){
    int n4=n/4;
    split_bf16<<<(n4+255)/256,256>>>((const float4*)s,(uint2*)h,(uint2*)l,n4);
}
template<typename T> static T* sym(T* s){ void* p; cudaGetSymbolAddress(&p,(const void*)s); return (T*)p; }
}

extern "C" void kernel_launch(void* const* d_in, const int* in_sizes, int n_in,
                              void* d_out, int out_size)
{
    (void)in_sizes;(void)n_in;(void)out_size;
    const float* app=(const float*)d_in[0]; const float* mot=(const float*)d_in[1];
    const float* qe=(const float*)d_in[2];  const float* Wq=(const float*)d_in[3];
    const float* bq=(const float*)d_in[4];  const float* Wm=(const float*)d_in[5];
    const float* bmv=(const float*)d_in[6]; const float* Wa=(const float*)d_in[7];
    const float* ba=(const float*)d_in[8];  const float* Wvm=(const float*)d_in[9];
    const float* bvm=(const float*)d_in[10];const float* Wih=(const float*)d_in[11];
    const float* Whh=(const float*)d_in[12];const float* bih=(const float*)d_in[13];
    const float* bhh=(const float*)d_in[14];const float* W1=(const float*)d_in[15];
    const float* b1=(const float*)d_in[16]; const float* W2=(const float*)d_in[17];
    const float* b2=(const float*)d_in[18]; const float* gW2=(const float*)d_in[19];
    const float* gb2=(const float*)d_in[20];const float* W3=(const float*)d_in[21];
    const float* b3=(const float*)d_in[22]; const float* W4=(const float*)d_in[23];
    const float* b4=(const float*)d_in[24]; const float* gW4=(const float*)d_in[25];
    const float* gb4=(const float*)d_in[26];
    float* outp=(float*)d_out;

    cudaFuncSetAttribute(tgemm, cudaFuncAttributeMaxDynamicSharedMemorySize, (int)TG_SMEM);

    u64 Bn[17][17]={};
    for(int i=0;i<=16;i++){ Bn[i][0]=1;
        for(int j=1;j<=i;j++) Bn[i][j]=Bn[i-1][j-1]+((j<=i-1)?Bn[i-1][j]:0ull); }
    MaskArgs ma1,ma2,ma3,ma4;
    {
        MT19937 rng; rng.seed(0);
        auto doCall=[&](int n,int steps,MaskArgs& o){
            for(int s=0;s<steps;s++){
                int scale=n-(s+1); int pop=(int)Bn[n][scale];
                int r=perm_first(rng,pop);
                o.m[s]=unrank_mask(n,scale,(long long)r,Bn);
                o.inv[s]=1.0f/(float)scale;
            }
        };
        doCall(16,14,ma1); doCall(14,12,ma2); doCall(8,6,ma3); doCall(6,4,ma4);
    }

    float *p_app=sym(g_app),*p_motproj=sym(g_motproj),*p_qproj=sym(g_qproj),
          *p_objs2=sym(g_objs2),*p_clip=sym(g_clip),*p_gatesx=sym(g_gatesx),
          *p_gates=sym(g_gates),*p_hst=sym(g_hstate),*p_cst=sym(g_cstate),
          *p_vm=sym(g_vm),*p_objs4=sym(g_objs4);
    bf16 *appH=sym(b_appH),*appL=sym(b_appL),*motH=sym(b_motH),*motL=sym(b_motL),
         *WaH=sym(b_WaH),*WaL=sym(b_WaL),*WmH=sym(b_WmH),*WmL=sym(b_WmL),
         *WihH=sym(b_WihH),*WihL=sym(b_WihL),
         *W1H=sym(b_W1H),*W1L=sym(b_W1L),*W2H=sym(b_W2H),*W2L=sym(b_W2L),
         *gW2H=sym(b_gW2H),*gW2L=sym(b_gW2L),*W3H=sym(b_W3H),*W3L=sym(b_W3L),
         *W4H=sym(b_W4H),*W4L=sym(b_W4L),*gW4H=sym(b_gW4H),*gW4L=sym(b_gW4L),
         *catH=sym(b_catH),*catL=sym(b_catL);

    split(app,appH,appL,16384*2048); split(mot,motH,motL,1024*2048);
    split(Wa,WaH,WaL,512*2048); split(Wm,WmH,WmL,512*2048);
    split(Wih,WihH,WihL,2048*2048);
    split(W1,W1H,W1L,15*512*1024); split(W2,W2H,W2L,13*512*1024);
    split(gW2,gW2H,gW2L,13*512*1024); split(W3,W3H,W3L,7*512*1024);
    split(W4,W4H,W4L,5*512*1024); split(gW4,gW4H,gW4L,5*512*1024);

    { dim3 g(8,2); sgemm_small<<<g,256>>>(qe,512,Wq,bq,nullptr,0,p_qproj,512,512,0); }
    launch_t(motH,motL,0,2048, WmH,WmL,0, bmv,0, p_motproj,0, 1024,0,512, 1024,512,2048,1,0);
    launch_t(appH,appL,0,2048, WaH,WaL,0, ba,0,  p_app,0,     16384,0,512,16384,512,2048,1,0);
    launch_t(motH,motL,0,2048, WihH,WihL,0, bih,0, p_gatesx,0, 1024,0,2048,1024,2048,2048,1,0);

    const long long WS=512*1024;
    // crn_m: 14 steps
    mean_subset_bf16<<<dim3(512,14),256>>>((uint2*)catH,(uint2*)catL,p_app,1024,0,16*512,512,ma1,1024);
    cond_fill_bf16<<<dim3(512,14),256>>>((uint2*)catH,(uint2*)catL,p_motproj,1,1024);
    launch_t(catH,catL,1024LL*1024,1024, W1H+WS,W1L+WS,WS, b1+512,512,
             p_objs2,512, 1024,0,14*512, 1024,512,1024,14,1);
    // crn_q: 12 gated steps
    mean_subset_bf16<<<dim3(512,12),256>>>((uint2*)catH,(uint2*)catL,p_objs2,1024,0,14*512,512,ma2,1024);
    cond_fill_bf16<<<dim3(512,12),256>>>((uint2*)catH,(uint2*)catL,p_qproj,8,1024);
    launch_t(catH,catL,1024LL*1024,1024, W2H+WS,W2L+WS,WS, b2+512,512,
             p_clip,512, 1024,0,12*512, 1024,512,1024,12,1);
    launch_t(catH,catL,1024LL*1024,1024, gW2H+WS,gW2L+WS,WS, gb2+512,512,
             p_clip,512, 1024,0,12*512, 1024,512,1024,12,2);
    // LSTM
    zero_kernel<<<256,256>>>(p_hst,128*512);
    zero_kernel<<<256,256>>>(p_cst,128*512);
    for(int t=0;t<8;t++){
        dim3 g(32,2);
        sgemm_small<<<g,256>>>(p_hst,512,Whh,bhh,p_gatesx+(size_t)t*2048,8*2048,p_gates,2048,512,3);
        lstm_cell_kernel<<<256,256>>>(p_gates,p_hst,p_cst);
    }
    { dim3 g(8,2); sgemm_small<<<g,256>>>(p_hst,512,Wvm,bvm,nullptr,0,p_vm,512,512,0); }
    // crn_vm: 6 steps
    mean_subset_bf16<<<dim3(768,6),256>>>((uint2*)catH,(uint2*)catL,p_clip,12,8*12*512,512,12*512,ma3,1536);
    cond_fill_bf16<<<dim3(768,6),256>>>((uint2*)catH,(uint2*)catL,p_vm,12,1536);
    launch_t(catH,catL,1536LL*1024,1024, W3H+WS,W3L+WS,WS, b3+512,512,
             p_objs4,12*512, 12,6*12*512,512, 1536,512,1024,6,1);
    // crn_vq: 4 gated steps -> out
    mean_subset_bf16<<<dim3(768,4),256>>>((uint2*)catH,(uint2*)catL,p_objs4,12,6*12*512,512,12*512,ma4,1536);
    cond_fill_bf16<<<dim3(768,4),256>>>((uint2*)catH,(uint2*)catL,p_qproj,12,1536);
    launch_t(catH,catL,1536LL*1024,1024, W4H+WS,W4L+WS,WS, b4+512,512,
             outp,12*512, 12,48*512,512, 1536,512,1024,4,1);
    launch_t(catH,catL,1536LL*1024,1024, gW4H+WS,gW4L+WS,WS, gb4+512,512,
             outp,12*512, 12,48*512,512, 1536,512,1024,4,2);
}

// round 9
// speedup vs baseline: 2.6979x; 1.2594x over previous
#include <cuda_runtime.h>
#include <cuda_fp16.h>
#include <cstdint>
#include <cstddef>
typedef unsigned long long u64;
typedef uint32_t u32;

__device__ __align__(256) float g_app[16384*512];
__device__ __align__(256) float g_motproj[1024*512];
__device__ __align__(256) float g_qproj[128*512];
__device__ __align__(256) float g_objs2[1024*14*512];
__device__ __align__(256) float g_clip[1024*12*512];
__device__ __align__(256) float g_gatesx[1024*2048];
__device__ __align__(256) float g_gates[128*2048];
__device__ __align__(256) float g_hstate[128*512];
__device__ __align__(256) float g_cstate[128*512];
__device__ __align__(256) float g_vm[128*512];
__device__ __align__(256) float g_objs4[128*6*12*512];
// A-side fp16 hi/lo splits
__device__ __align__(256) __half a_appH[16384*2048], a_appL[16384*2048];
__device__ __align__(256) __half a_motH[1024*2048],  a_motL[1024*2048];
__device__ __align__(256) __half a_catH[14336*1024], a_catL[14336*1024];
// W-side single fp16
__device__ __align__(256) __half w_Wa[512*2048];
__device__ __align__(256) __half w_Wm[512*2048];
__device__ __align__(256) __half w_Wih[2048*2048];
__device__ __align__(256) __half w_W1[15*512*1024];
__device__ __align__(256) __half w_W2[13*512*1024];
__device__ __align__(256) __half w_gW2[13*512*1024];
__device__ __align__(256) __half w_W3[7*512*1024];
__device__ __align__(256) __half w_W4[5*512*1024];
__device__ __align__(256) __half w_gW4[5*512*1024];

struct MaskArgs { unsigned m[14]; float inv[14]; };

static __device__ __forceinline__ u32 sm_u32(const void* p){
    u32 a; asm("{ .reg .u64 t; cvta.to.shared.u64 t, %1; cvt.u32.u64 %0, t; }":"=r"(a):"l"(p)); return a;
}
#define SW128(o) ((o) ^ (((o) >> 3) & 0x70))
static __device__ __forceinline__ void cpa(u32 s, const void* g){
    asm volatile("cp.async.cg.shared.global [%0], [%1], 16;" :: "r"(s), "l"(g) : "memory");
}
static __device__ __forceinline__ void ldm4(u32* r, u32 a){
    asm volatile("ldmatrix.sync.aligned.m8n8.x4.shared.b16 {%0,%1,%2,%3}, [%4];"
        : "=r"(r[0]),"=r"(r[1]),"=r"(r[2]),"=r"(r[3]) : "r"(a));
}
static __device__ __forceinline__ void mma_f16(float* d, const u32* a, const u32* b){
    asm volatile("mma.sync.aligned.m16n8k16.row.col.f32.f16.f16.f32 "
        "{%0,%1,%2,%3}, {%4,%5,%6,%7}, {%8,%9}, {%0,%1,%2,%3};"
        : "+f"(d[0]),"+f"(d[1]),"+f"(d[2]),"+f"(d[3])
        : "r"(a[0]),"r"(a[1]),"r"(a[2]),"r"(a[3]), "r"(b[0]),"r"(b[1]));
}
// pack 4 floats -> fp16 hi (uint2) and fp16 residual lo (uint2)
static __device__ __forceinline__ void pack_hl16(const float* a, uint2& H, uint2& L){
    __half h0=__float2half_rn(a[0]), h1=__float2half_rn(a[1]);
    __half h2=__float2half_rn(a[2]), h3=__float2half_rn(a[3]);
    __half2 hp0=__halves2half2(h0,h1), hp1=__halves2half2(h2,h3);
    H.x=*(u32*)&hp0; H.y=*(u32*)&hp1;
    __half l0=__float2half_rn(a[0]-__half2float(h0));
    __half l1=__float2half_rn(a[1]-__half2float(h1));
    __half l2=__float2half_rn(a[2]-__half2float(h2));
    __half l3=__float2half_rn(a[3]-__half2float(h3));
    __half2 lp0=__halves2half2(l0,l1), lp1=__halves2half2(l2,l3);
    L.x=*(u32*)&lp0; L.y=*(u32*)&lp1;
}

// ---- tensor GEMM: C=act((Ah+Al)@W^T + bias), fp16 ops / fp32 accum ----
// A split 2-term; W single fp16. Tile 128x128, Ktile 64, 2-stage cp.async.
__global__ void __launch_bounds__(256,2)
tgemm(const __half* __restrict__ Ah, const __half* __restrict__ Al, long long A_step, int lda,
      const __half* __restrict__ W, long long W_step,
      const float* __restrict__ bias, long long bias_step,
      float* __restrict__ C, long long C_step,
      int c_inner, long long c_so, long long c_sr, int K, int act)
{
    extern __shared__ char dsm[];
    const int tid=threadIdx.x, wid=tid>>5, lane=tid&31;
    const int wm=wid>>2, wn=wid&3;
    const int bm=blockIdx.y*128, bn=blockIdx.x*128, step=blockIdx.z;
    Ah+=(size_t)step*A_step; Al+=(size_t)step*A_step;
    W+=(size_t)step*W_step;
    bias+=(size_t)step*bias_step; C+=(size_t)step*C_step;
    u32 raw=sm_u32(dsm), pad=((raw+1023u)&~1023u)-raw;
    const u32 base=raw+pad;
    const u32 STAGE=49152u;

    float acc[4][4][4];
#pragma unroll
    for(int i=0;i<4;i++)
#pragma unroll
    for(int j=0;j<4;j++)
#pragma unroll
    for(int k=0;k<4;k++) acc[i][j][k]=0.f;

    const int ntiles=K>>6;
    {
        const u32 stg=base; const int k0=0;
#pragma unroll
        for(int i=0;i<4;i++){
            int q=tid+i*256, row=q>>3, c16=q&7;
            u32 so=SW128((u32)(row*128+c16*16));
            size_t ao=(size_t)(bm+row)*lda+k0+c16*8;
            size_t wo=(size_t)(bn+row)*K+k0+c16*8;
            cpa(stg+so,Ah+ao); cpa(stg+16384+so,Al+ao); cpa(stg+32768+so,W+wo);
        }
        asm volatile("cp.async.commit_group;" ::: "memory");
    }
    for(int t=0;t<ntiles;t++){
        if(t+1<ntiles){
            const u32 stg=base+((t+1)&1)*STAGE; const int k0=(t+1)<<6;
#pragma unroll
            for(int i=0;i<4;i++){
                int q=tid+i*256, row=q>>3, c16=q&7;
                u32 so=SW128((u32)(row*128+c16*16));
                size_t ao=(size_t)(bm+row)*lda+k0+c16*8;
                size_t wo=(size_t)(bn+row)*K+k0+c16*8;
                cpa(stg+so,Ah+ao); cpa(stg+16384+so,Al+ao); cpa(stg+32768+so,W+wo);
            }
            asm volatile("cp.async.commit_group;" ::: "memory");
            asm volatile("cp.async.wait_group 1;" ::: "memory");
        } else {
            asm volatile("cp.async.wait_group 0;" ::: "memory");
        }
        __syncthreads();
        const u32 stg=base+(t&1)*STAGE;
        const int sub=lane>>3, l7=lane&7;
        const int arow=(sub&1)*8+l7, akb=(sub>>1)*16;
        const int brow=(sub>>1)*8+l7, bkb=(sub&1)*16;
#pragma unroll
        for(int ks=0;ks<4;ks++){
            u32 br[2][4];
#pragma unroll
            for(int p=0;p<2;p++){
                int row=wn*32+p*16+brow;
                u32 so=SW128((u32)(row*128+ks*32+bkb));
                ldm4(br[p], stg+32768+so);
            }
#pragma unroll
            for(int mt=0;mt<4;mt++){
                int row=wm*64+mt*16+arow;
                u32 so=SW128((u32)(row*128+ks*32+akb));
                u32 ah[4], al[4];
                ldm4(ah, stg+so);
                ldm4(al, stg+16384+so);
#pragma unroll
                for(int nt=0;nt<4;nt++){
                    int p=nt>>1, h=(nt&1)*2;
                    mma_f16(acc[mt][nt], ah, &br[p][h]);
                    mma_f16(acc[mt][nt], al, &br[p][h]);
                }
            }
        }
        __syncthreads();
    }
#pragma unroll
    for(int mt=0;mt<4;mt++){
        int mrow=bm+wm*64+mt*16+(lane>>2);
#pragma unroll
        for(int hf=0;hf<2;hf++){
            int m=mrow+hf*8;
            size_t crow=(size_t)(m/c_inner)*(size_t)c_so+(size_t)(m%c_inner)*(size_t)c_sr;
#pragma unroll
            for(int nt=0;nt<4;nt++){
                int n=bn+wn*32+nt*8+(lane&3)*2;
                float v0=acc[mt][nt][hf*2+0]+bias[n];
                float v1=acc[mt][nt][hf*2+1]+bias[n+1];
                float* cp0=C+crow+n;
                if(act==0){ cp0[0]=v0; cp0[1]=v1; }
                else if(act==1){
                    cp0[0]=(v0>0.f)?v0:expm1f(v0);
                    cp0[1]=(v1>0.f)?v1:expm1f(v1);
                } else {
                    cp0[0]*=1.f/(1.f+expf(-v0));
                    cp0[1]*=1.f/(1.f+expf(-v1));
                }
            }
        }
    }
}

// ---- vectorized converts ----
__global__ void split_f16(const float4* __restrict__ s, uint2* __restrict__ h,
                          uint2* __restrict__ l, int n4){
    int i=blockIdx.x*blockDim.x+threadIdx.x;
    if(i>=n4) return;
    float4 v=s[i]; float a[4]={v.x,v.y,v.z,v.w};
    uint2 H,L; pack_hl16(a,H,L);
    h[i]=H; l[i]=L;
}
__global__ void conv_f16(const float4* __restrict__ s, uint2* __restrict__ w, int n4){
    int i=blockIdx.x*blockDim.x+threadIdx.x;
    if(i>=n4) return;
    float4 v=s[i];
    __half2 p0=__halves2half2(__float2half_rn(v.x),__float2half_rn(v.y));
    __half2 p1=__halves2half2(__float2half_rn(v.z),__float2half_rn(v.w));
    uint2 o; o.x=*(u32*)&p0; o.y=*(u32*)&p1;
    w[i]=o;
}
__global__ void mean_subset_f16(uint2* __restrict__ h, uint2* __restrict__ l,
    const float* __restrict__ objs, int inner, long long sB, long long sR, long long sJ,
    MaskArgs ma, int M){
    int step=blockIdx.y, idx=blockIdx.x*blockDim.x+threadIdx.x;
    int m=idx>>7, d4=(idx&127)<<2;
    if(m>=M) return;
    unsigned mm=ma.m[step]; float inv=ma.inv[step];
    const float* bp=objs+(size_t)(m/inner)*sB+(size_t)(m%inner)*sR+d4;
    float s0=0,s1=0,s2=0,s3=0;
    while(mm){ int j=__ffs((int)mm)-1; mm&=mm-1;
        float4 v=*(const float4*)(bp+(size_t)j*sJ); s0+=v.x;s1+=v.y;s2+=v.z;s3+=v.w; }
    float a[4]={s0*inv,s1*inv,s2*inv,s3*inv};
    uint2 H,L; pack_hl16(a,H,L);
    size_t o=(((size_t)step*M+m)*1024+d4)>>2;
    h[o]=H; l[o]=L;
}
__global__ void cond_fill_f16(uint2* __restrict__ h, uint2* __restrict__ l,
    const float* __restrict__ cond, int div, int M){
    int step=blockIdx.y, idx=blockIdx.x*blockDim.x+threadIdx.x;
    int m=idx>>7, d4=(idx&127)<<2;
    if(m>=M) return;
    float4 v=*(const float4*)(cond+(size_t)(m/div)*512+d4);
    float a[4]={v.x,v.y,v.z,v.w};
    uint2 H,L; pack_hl16(a,H,L);
    size_t o=(((size_t)step*M+m)*1024+512+d4)>>2;
    h[o]=H; l[o]=L;
}
__global__ void zero_kernel(float* p, int n){
    int i=blockIdx.x*blockDim.x+threadIdx.x; if(i<n) p[i]=0.f;
}
__global__ void lstm_cell_kernel(const float* __restrict__ g, float* __restrict__ h, float* __restrict__ c){
    int idx=blockIdx.x*blockDim.x+threadIdx.x;
    int m=idx>>9, d=idx&511;
    const float* gr=g+(size_t)m*2048;
    float ig=1.f/(1.f+expf(-gr[d])), fg=1.f/(1.f+expf(-gr[512+d]));
    float gg=tanhf(gr[1024+d]), og=1.f/(1.f+expf(-gr[1536+d]));
    float cn=fg*c[idx]+ig*gg;
    c[idx]=cn; h[idx]=og*tanhf(cn);
}
// ---- SIMT small GEMM (qproj/LSTM/vm); act: 0 none | 3 +=add ----
__global__ void __launch_bounds__(256)
sgemm_small(const float* __restrict__ A, int lda, const float* __restrict__ W,
            const float* __restrict__ bias, const float* __restrict__ add, long long add_sr,
            float* __restrict__ C, long long c_sr, int K, int act)
{
    constexpr int BM=64, BK=16;
    __shared__ __align__(16) float As[BK][BM];
    __shared__ __align__(16) float Bs[BK][BM];
    const int bm=blockIdx.y*BM, bn=blockIdx.x*BM;
    const int tid=threadIdx.x, tx=tid&15, ty=tid>>4;
    u64 acc[4][2];
#pragma unroll
    for(int i=0;i<4;i++){acc[i][0]=0ull;acc[i][1]=0ull;}
    for(int k0=0;k0<K;k0+=BK){
        { int r=tid>>2, c4=(tid&3)<<2;
          float4 va=*(const float4*)(A+(size_t)(bm+r)*lda+k0+c4);
          As[c4+0][r]=va.x;As[c4+1][r]=va.y;As[c4+2][r]=va.z;As[c4+3][r]=va.w;
          float4 vb=*(const float4*)(W+(size_t)(bn+r)*K+k0+c4);
          Bs[c4+0][r]=vb.x;Bs[c4+1][r]=vb.y;Bs[c4+2][r]=vb.z;Bs[c4+3][r]=vb.w; }
        __syncthreads();
#pragma unroll
        for(int kk=0;kk<BK;kk++){
            float4 a0=*(const float4*)(&As[kk][ty*4]);
            float av[4]={a0.x,a0.y,a0.z,a0.w};
            double2 b0=*(const double2*)(&Bs[kk][tx*4]);
            u64 bp[2]={(u64)__double_as_longlong(b0.x),(u64)__double_as_longlong(b0.y)};
#pragma unroll
            for(int i=0;i<4;i++){
                u64 ap; asm("mov.b64 %0, {%1, %1};":"=l"(ap):"r"(__float_as_uint(av[i])));
                asm("fma.rn.f32x2 %0, %1, %2, %0;":"+l"(acc[i][0]):"l"(ap),"l"(bp[0]));
                asm("fma.rn.f32x2 %0, %1, %2, %0;":"+l"(acc[i][1]):"l"(ap),"l"(bp[1]));
            }
        }
        __syncthreads();
    }
#pragma unroll
    for(int i=0;i<4;i++){
        int m=bm+ty*4+i;
#pragma unroll
        for(int j=0;j<4;j++){
            int n=bn+tx*4+j;
            u64 pk=acc[i][j>>1];
            unsigned lv=(j&1)?(unsigned)(pk>>32):(unsigned)pk;
            float v=__uint_as_float(lv)+bias[n];
            if(act==3) v+=add[(size_t)m*add_sr+n];
            C[(size_t)m*c_sr+n]=v;
        }
    }
}

namespace {
struct MT19937 {
    unsigned mt[624]; int pos;
    void seed(unsigned s){ for(int i=0;i<624;i++){mt[i]=s; s=1812433253u*(s^(s>>30))+(unsigned)i+1u;} pos=624; }
    unsigned next(){
        if(pos>=624){ for(int i=0;i<624;i++){
            unsigned y=(mt[i]&0x80000000u)|(mt[(i+1)%624]&0x7fffffffu);
            unsigned v=mt[(i+397)%624]^(y>>1); if(y&1u)v^=0x9908b0dfu; mt[i]=v; } pos=0; }
        unsigned y=mt[pos++];
        y^=y>>11; y^=(y<<7)&0x9d2c5680u; y^=(y<<15)&0xefc60000u; y^=y>>18; return y;
    }
    unsigned interval(unsigned mx){
        if(!mx) return 0;
        unsigned m=mx; m|=m>>1;m|=m>>2;m|=m>>4;m|=m>>8;m|=m>>16;
        unsigned v; do{v=next()&m;}while(v>mx); return v;
    }
};
static int perm_first(MT19937& r,int n){
    static int arr[13000];
    for(int i=0;i<n;i++)arr[i]=i;
    for(int i=n-1;i>0;i--){int j=(int)r.interval((unsigned)i);int t=arr[i];arr[i]=arr[j];arr[j]=t;}
    return arr[0];
}
static unsigned unrank_mask(int n,int k,long long idx,const u64 Bn[17][17]){
    unsigned mask=0;int x=0;
    for(int i=0;i<k;i++) for(int v=x;;v++){
        long long c=(long long)Bn[n-1-v][k-1-i];
        if(idx<c){mask|=1u<<v;x=v+1;break;} idx-=c; }
    return mask;
}
constexpr size_t TG_SMEM = 2*49152 + 1024;
static void launch_t(const __half* Ah,const __half* Al,long long A_step,int lda,
                     const __half* W,long long W_step,
                     const float* bias,long long bias_step,
                     float* C,long long C_step,int c_inner,long long c_so,long long c_sr,
                     int M,int N,int K,int steps,int act){
    dim3 g(N/128, M/128, steps);
    tgemm<<<g,256,TG_SMEM>>>(Ah,Al,A_step,lda,W,W_step,bias,bias_step,C,C_step,c_inner,c_so,c_sr,K,act);
}
static void splitA(const float* s, __half* h, __half* l, int n){
    int n4=n/4;
    split_f16<<<(n4+255)/256,256>>>((const float4*)s,(uint2*)h,(uint2*)l,n4);
}
static void convW(const float* s, __half* w, int n){
    int n4=n/4;
    conv_f16<<<(n4+255)/256,256>>>((const float4*)s,(uint2*)w,n4);
}
template<typename T> static T* sym(T* s){ void* p; cudaGetSymbolAddress(&p,(const void*)s); return (T*)p; }
}

extern "C" void kernel_launch(void* const* d_in, const int* in_sizes, int n_in,
                              void* d_out, int out_size)
{
    (void)in_sizes;(void)n_in;(void)out_size;
    const float* app=(const float*)d_in[0]; const float* mot=(const float*)d_in[1];
    const float* qe=(const float*)d_in[2];  const float* Wq=(const float*)d_in[3];
    const float* bq=(const float*)d_in[4];  const float* Wm=(const float*)d_in[5];
    const float* bmv=(const float*)d_in[6]; const float* Wa=(const float*)d_in[7];
    const float* ba=(const float*)d_in[8];  const float* Wvm=(const float*)d_in[9];
    const float* bvm=(const float*)d_in[10];const float* Wih=(const float*)d_in[11];
    const float* Whh=(const float*)d_in[12];const float* bih=(const float*)d_in[13];
    const float* bhh=(const float*)d_in[14];const float* W1=(const float*)d_in[15];
    const float* b1=(const float*)d_in[16]; const float* W2=(const float*)d_in[17];
    const float* b2=(const float*)d_in[18]; const float* gW2=(const float*)d_in[19];
    const float* gb2=(const float*)d_in[20];const float* W3=(const float*)d_in[21];
    const float* b3=(const float*)d_in[22]; const float* W4=(const float*)d_in[23];
    const float* b4=(const float*)d_in[24]; const float* gW4=(const float*)d_in[25];
    const float* gb4=(const float*)d_in[26];
    float* outp=(float*)d_out;

    cudaFuncSetAttribute(tgemm, cudaFuncAttributeMaxDynamicSharedMemorySize, (int)TG_SMEM);

    u64 Bn[17][17]={};
    for(int i=0;i<=16;i++){ Bn[i][0]=1;
        for(int j=1;j<=i;j++) Bn[i][j]=Bn[i-1][j-1]+((j<=i-1)?Bn[i-1][j]:0ull); }
    MaskArgs ma1,ma2,ma3,ma4;
    {
        MT19937 rng; rng.seed(0);
        auto doCall=[&](int n,int steps,MaskArgs& o){
            for(int s=0;s<steps;s++){
                int scale=n-(s+1); int pop=(int)Bn[n][scale];
                int r=perm_first(rng,pop);
                o.m[s]=unrank_mask(n,scale,(long long)r,Bn);
                o.inv[s]=1.0f/(float)scale;
            }
        };
        doCall(16,14,ma1); doCall(14,12,ma2); doCall(8,6,ma3); doCall(6,4,ma4);
    }

    float *p_app=sym(g_app),*p_motproj=sym(g_motproj),*p_qproj=sym(g_qproj),
          *p_objs2=sym(g_objs2),*p_clip=sym(g_clip),*p_gatesx=sym(g_gatesx),
          *p_gates=sym(g_gates),*p_hst=sym(g_hstate),*p_cst=sym(g_cstate),
          *p_vm=sym(g_vm),*p_objs4=sym(g_objs4);
    __half *appH=sym(a_appH),*appL=sym(a_appL),*motH=sym(a_motH),*motL=sym(a_motL),
           *catH=sym(a_catH),*catL=sym(a_catL),
           *WaF=sym(w_Wa),*WmF=sym(w_Wm),*WihF=sym(w_Wih),
           *W1F=sym(w_W1),*W2F=sym(w_W2),*gW2F=sym(w_gW2),*W3F=sym(w_W3),
           *W4F=sym(w_W4),*gW4F=sym(w_gW4);

    splitA(app,appH,appL,16384*2048); splitA(mot,motH,motL,1024*2048);
    convW(Wa,WaF,512*2048); convW(Wm,WmF,512*2048); convW(Wih,WihF,2048*2048);
    convW(W1,W1F,15*512*1024); convW(W2,W2F,13*512*1024);
    convW(gW2,gW2F,13*512*1024); convW(W3,W3F,7*512*1024);
    convW(W4,W4F,5*512*1024); convW(gW4,gW4F,5*512*1024);

    { dim3 g(8,2); sgemm_small<<<g,256>>>(qe,512,Wq,bq,nullptr,0,p_qproj,512,512,0); }
    launch_t(motH,motL,0,2048, WmF,0, bmv,0, p_motproj,0, 1024,0,512, 1024,512,2048,1,0);
    launch_t(appH,appL,0,2048, WaF,0, ba,0,  p_app,0,     16384,0,512,16384,512,2048,1,0);
    launch_t(motH,motL,0,2048, WihF,0, bih,0, p_gatesx,0, 1024,0,2048,1024,2048,2048,1,0);

    const long long WS=512*1024;
    // crn_m: 14 steps
    mean_subset_f16<<<dim3(512,14),256>>>((uint2*)catH,(uint2*)catL,p_app,1024,0,16*512,512,ma1,1024);
    cond_fill_f16<<<dim3(512,14),256>>>((uint2*)catH,(uint2*)catL,p_motproj,1,1024);
    launch_t(catH,catL,1024LL*1024,1024, W1F+WS,WS, b1+512,512,
             p_objs2,512, 1024,0,14*512, 1024,512,1024,14,1);
    // crn_q: 12 gated steps
    mean_subset_f16<<<dim3(512,12),256>>>((uint2*)catH,(uint2*)catL,p_objs2,1024,0,14*512,512,ma2,1024);
    cond_fill_f16<<<dim3(512,12),256>>>((uint2*)catH,(uint2*)catL,p_qproj,8,1024);
    launch_t(catH,catL,1024LL*1024,1024, W2F+WS,WS, b2+512,512,
             p_clip,512, 1024,0,12*512, 1024,512,1024,12,1);
    launch_t(catH,catL,1024LL*1024,1024, gW2F+WS,WS, gb2+512,512,
             p_clip,512, 1024,0,12*512, 1024,512,1024,12,2);
    // LSTM
    zero_kernel<<<256,256>>>(p_hst,128*512);
    zero_kernel<<<256,256>>>(p_cst,128*512);
    for(int t=0;t<8;t++){
        dim3 g(32,2);
        sgemm_small<<<g,256>>>(p_hst,512,Whh,bhh,p_gatesx+(size_t)t*2048,8*2048,p_gates,2048,512,3);
        lstm_cell_kernel<<<256,256>>>(p_gates,p_hst,p_cst);
    }
    { dim3 g(8,2); sgemm_small<<<g,256>>>(p_hst,512,Wvm,bvm,nullptr,0,p_vm,512,512,0); }
    // crn_vm: 6 steps
    mean_subset_f16<<<dim3(768,6),256>>>((uint2*)catH,(uint2*)catL,p_clip,12,8*12*512,512,12*512,ma3,1536);
    cond_fill_f16<<<dim3(768,6),256>>>((uint2*)catH,(uint2*)catL,p_vm,12,1536);
    launch_t(catH,catL,1536LL*1024,1024, W3F+WS,WS, b3+512,512,
             p_objs4,12*512, 12,6*12*512,512, 1536,512,1024,6,1);
    // crn_vq: 4 gated steps -> out
    mean_subset_f16<<<dim3(768,4),256>>>((uint2*)catH,(uint2*)catL,p_objs4,12,6*12*512,512,12*512,ma4,1536);
    cond_fill_f16<<<dim3(768,4),256>>>((uint2*)catH,(uint2*)catL,p_qproj,12,1536);
    launch_t(catH,catL,1536LL*1024,1024, W4F+WS,WS, b4+512,512,
             outp,12*512, 12,48*512,512, 1536,512,1024,4,1);
    launch_t(catH,catL,1536LL*1024,1024, gW4F+WS,WS, gb4+512,512,
             outp,12*512, 12,48*512,512, 1536,512,1024,4,2);
}